// round 5
// baseline (speedup 1.0000x reference)
#include <cuda_runtime.h>
#include <math.h>
#include <stdint.h>

// Problem constants
#define T_       1024
#define D_       1024
#define E_       16
#define K_SEL    4
#define NGRP     4
#define INTER_   512
#define SH_INTER 1024
#define RSCALE   2.5f

#define LDP 36                        // padded smem row stride (floats)
#define BUFB (128 * LDP * 4)          // one buffer (A or B plane), bytes
#define NSTAGE 3
#define NZ   18                       // 16 routed experts + 2 shared halves

// ---------------- device scratch ----------------
__device__ int   g_cnt[E_];
__device__ int   g_tok[E_ * T_];
__device__ float g_wt [E_ * T_];
__device__ float g_inter[(size_t)E_ * T_ * INTER_];
__device__ float g_hsh[(size_t)T_ * SH_INTER];

// ---------------- helpers ----------------
__device__ __forceinline__ uint32_t smem_u32(const void* p) {
    uint32_t a;
    asm("{ .reg .u64 t; cvta.to.shared.u64 t, %1; cvt.u32.u64 %0, t; }" : "=r"(a) : "l"(p));
    return a;
}
__device__ __forceinline__ void cp16(uint32_t s, const float* g) {
    asm volatile("cp.async.cg.shared.global [%0], [%1], 16;" :: "r"(s), "l"(g) : "memory");
}
#define CP_COMMIT() asm volatile("cp.async.commit_group;" ::: "memory")
#define CP_WAIT(n)  asm volatile("cp.async.wait_group %0;" :: "n"(n) : "memory")

__device__ __forceinline__ uint32_t lds_tf32(const float* p) {
    uint32_t u;
    asm("cvt.rna.tf32.f32 %0, %1;" : "=r"(u) : "f"(*p));
    return u;
}
__device__ __forceinline__ void mma_tf32(float c[4],
                                         uint32_t a0, uint32_t a1, uint32_t a2, uint32_t a3,
                                         uint32_t b0, uint32_t b1) {
    asm volatile(
        "mma.sync.aligned.m16n8k8.row.col.f32.tf32.tf32.f32 "
        "{%0,%1,%2,%3}, {%4,%5,%6,%7}, {%8,%9}, {%0,%1,%2,%3};"
        : "+f"(c[0]), "+f"(c[1]), "+f"(c[2]), "+f"(c[3])
        : "r"(a0), "r"(a1), "r"(a2), "r"(a3), "r"(b0), "r"(b1));
}
__device__ __forceinline__ float silu_mul(float g, float u) {
    return g / (1.f + expf(-g)) * u;
}

// ---------------- routing ----------------
__global__ void zero_counts_kernel() {
    if (threadIdx.x < E_) g_cnt[threadIdx.x] = 0;
}

__global__ void route_kernel(const float* __restrict__ x,
                             const float* __restrict__ gw,
                             const float* __restrict__ gb) {
    const int t = blockIdx.x;
    __shared__ float xs[D_];
    __shared__ float sc[E_];
    const int tid = threadIdx.x;  // 128
    const float4* xr = (const float4*)(x + (size_t)t * D_);
    float4* xs4 = (float4*)xs;
    for (int i = tid; i < D_ / 4; i += 128) xs4[i] = xr[i];
    __syncthreads();

    const int warp = tid >> 5, lane = tid & 31;
    for (int e = warp * 4; e < warp * 4 + 4; e++) {
        const float* w = gw + (size_t)e * D_;
        float p = 0.f;
        for (int j = lane; j < D_; j += 32) p += xs[j] * w[j];
        #pragma unroll
        for (int o = 16; o; o >>= 1) p += __shfl_xor_sync(0xffffffffu, p, o);
        if (lane == 0) sc[e] = 1.f / (1.f + expf(-p));
    }
    __syncthreads();

    if (tid == 0) {
        float s[E_];
        #pragma unroll
        for (int e = 0; e < E_; e++) s[e] = sc[e] + gb[e];
        float gsc[NGRP];
        #pragma unroll
        for (int g = 0; g < NGRP; g++) {
            float m1 = -1e30f, m2 = -1e30f;
            #pragma unroll
            for (int j = 0; j < 4; j++) {
                float v = s[g * 4 + j];
                if (v > m1) { m2 = m1; m1 = v; } else if (v > m2) { m2 = v; }
            }
            gsc[g] = m1 + m2;
        }
        int g1 = 0;
        for (int g = 1; g < NGRP; g++) if (gsc[g] > gsc[g1]) g1 = g;
        int g2 = -1;
        for (int g = 0; g < NGRP; g++) {
            if (g == g1) continue;
            if (g2 < 0 || gsc[g] > gsc[g2]) g2 = g;
        }
        float masked[E_];
        #pragma unroll
        for (int e = 0; e < E_; e++) {
            int g = e >> 2;
            masked[e] = (g == g1 || g == g2) ? s[e] : 0.f;
        }
        int idx[K_SEL];
        float w[K_SEL];
        bool used[E_];
        #pragma unroll
        for (int e = 0; e < E_; e++) used[e] = false;
        float wsum = 0.f;
        for (int k = 0; k < K_SEL; k++) {
            int best = -1; float bv = -1e30f;
            for (int e = 0; e < E_; e++) {
                if (used[e]) continue;
                if (masked[e] > bv) { bv = masked[e]; best = e; }
            }
            used[best] = true;
            idx[k] = best;
            w[k] = sc[best];
            wsum += w[k];
        }
        const float scale = RSCALE / wsum;
        for (int k = 0; k < K_SEL; k++) {
            int e = idx[k];
            int pos = atomicAdd(&g_cnt[e], 1);
            g_tok[e * T_ + pos] = t;
            g_wt [e * T_ + pos] = w[k] * scale;
        }
    }
}

// ================================================================
// GEMM 1 (unified): z<16 routed expert z, z>=16 shared half (z-16).
// C = silu(X Wg^T) * (X Wu^T).  Block: 128 M x 64 N (gate), dual-B.
// 3-stage cp.async ring, one barrier per K-stage.
// ================================================================
__global__ void __launch_bounds__(256, 2) mma_gu_kernel(const float* __restrict__ X,
                                                        const float* __restrict__ gp,
                                                        const float* __restrict__ up,
                                                        const float* __restrict__ sg,
                                                        const float* __restrict__ su) {
    const int z = blockIdx.z;
    const bool routed = z < E_;
    const int cnt = routed ? g_cnt[z] : T_;
    const int m0  = blockIdx.y * 128;
    if (m0 >= cnt) return;
    const int n0 = blockIdx.x * 64;

    const float* Wg;
    const float* Wu;
    float* C;
    int ldc, cb;
    if (routed) {
        Wg = gp + ((size_t)z * INTER_ + n0) * D_;
        Wu = up + ((size_t)z * INTER_ + n0) * D_;
        C = g_inter + (size_t)z * T_ * INTER_;
        ldc = INTER_; cb = n0;
    } else {
        const int h = z - E_;
        Wg = sg + ((size_t)h * 512 + n0) * D_;
        Wu = su + ((size_t)h * 512 + n0) * D_;
        C = g_hsh;
        ldc = SH_INTER; cb = h * 512 + n0;
    }

    extern __shared__ float smem[];
    float* As = smem;                         // [NSTAGE][128][LDP]
    float* Bs = smem + NSTAGE * 128 * LDP;    // [NSTAGE][128][LDP]
    const uint32_t sA = smem_u32(As);
    const uint32_t sB = smem_u32(Bs);

    const int tid = threadIdx.x, wid = tid >> 5, lane = tid & 31;
    const int wm = wid >> 2, wn = wid & 3;

    // per-thread cp.async plan: 4 A + 4 B 16B-chunks per stage
    const float* agl[4]; const float* bgl[4];
    uint32_t sa[4], sbo[4];
    #pragma unroll
    for (int t = 0; t < 4; t++) {
        int it = tid + 256 * t;
        int row = it >> 3, c4 = it & 7;
        int mm = m0 + row; if (mm > cnt - 1) mm = cnt - 1;
        int ar = routed ? g_tok[z * T_ + mm] : mm;
        agl[t] = X + (size_t)ar * D_ + c4 * 4;
        bgl[t] = ((row < 64) ? (Wg + (size_t)row * D_) : (Wu + (size_t)(row - 64) * D_)) + c4 * 4;
        uint32_t boff = (uint32_t)(row * LDP + c4 * 4) * 4u;
        sa[t]  = sA + boff;
        sbo[t] = sB + boff;
    }

    float acg[4][2][4], acu[4][2][4];
    #pragma unroll
    for (int mi = 0; mi < 4; mi++)
        #pragma unroll
        for (int nj = 0; nj < 2; nj++)
            #pragma unroll
            for (int r = 0; r < 4; r++) { acg[mi][nj][r] = 0.f; acu[mi][nj][r] = 0.f; }

    const int NS = D_ / 32;   // 32 stages
    const int q = lane >> 2, c = lane & 3;

    // prologue: stages 0,1
    #pragma unroll
    for (int p = 0; p < 2; p++) {
        const uint32_t bo = (uint32_t)(p * BUFB);
        #pragma unroll
        for (int t = 0; t < 4; t++) { cp16(sa[t] + bo, agl[t] + p * 32); cp16(sbo[t] + bo, bgl[t] + p * 32); }
        CP_COMMIT();
    }

    int buf = 0, pbuf = 2;
    for (int s = 0; s < NS; s++) {
        if (s + 1 < NS) CP_WAIT(1); else CP_WAIT(0);
        __syncthreads();
        if (s + 2 < NS) {
            const uint32_t bo = (uint32_t)(pbuf * BUFB);
            #pragma unroll
            for (int t = 0; t < 4; t++) {
                cp16(sa[t] + bo, agl[t] + (s + 2) * 32);
                cp16(sbo[t] + bo, bgl[t] + (s + 2) * 32);
            }
            CP_COMMIT();
        }

        const float* Ab = As + buf * 128 * LDP;
        const float* Bb = Bs + buf * 128 * LDP;
        #pragma unroll
        for (int ks = 0; ks < 4; ks++) {
            const int kc = ks * 8 + c;
            uint32_t af[4][4];
            #pragma unroll
            for (int mi = 0; mi < 4; mi++) {
                const int r = wm * 64 + mi * 16 + q;
                af[mi][0] = lds_tf32(&Ab[r * LDP + kc]);
                af[mi][1] = lds_tf32(&Ab[(r + 8) * LDP + kc]);
                af[mi][2] = lds_tf32(&Ab[r * LDP + kc + 4]);
                af[mi][3] = lds_tf32(&Ab[(r + 8) * LDP + kc + 4]);
            }
            #pragma unroll
            for (int nj = 0; nj < 2; nj++) {
                const int n = wn * 16 + nj * 8 + q;
                uint32_t bg0 = lds_tf32(&Bb[n * LDP + kc]);
                uint32_t bg1 = lds_tf32(&Bb[n * LDP + kc + 4]);
                uint32_t bu0 = lds_tf32(&Bb[(n + 64) * LDP + kc]);
                uint32_t bu1 = lds_tf32(&Bb[(n + 64) * LDP + kc + 4]);
                #pragma unroll
                for (int mi = 0; mi < 4; mi++) {
                    mma_tf32(acg[mi][nj], af[mi][0], af[mi][1], af[mi][2], af[mi][3], bg0, bg1);
                    mma_tf32(acu[mi][nj], af[mi][0], af[mi][1], af[mi][2], af[mi][3], bu0, bu1);
                }
            }
        }
        buf = (buf == NSTAGE - 1) ? 0 : buf + 1;
        pbuf = (pbuf == NSTAGE - 1) ? 0 : pbuf + 1;
    }

    // epilogue: SwiGLU
    const int c2 = (lane & 3) * 2;
    #pragma unroll
    for (int mi = 0; mi < 4; mi++) {
        const int r0 = m0 + wm * 64 + mi * 16 + q;
        #pragma unroll
        for (int nj = 0; nj < 2; nj++) {
            const int col = cb + wn * 16 + nj * 8 + c2;
            if (r0 < cnt) {
                float2 v = make_float2(silu_mul(acg[mi][nj][0], acu[mi][nj][0]),
                                       silu_mul(acg[mi][nj][1], acu[mi][nj][1]));
                *(float2*)(C + (size_t)r0 * ldc + col) = v;
            }
            if (r0 + 8 < cnt) {
                float2 v = make_float2(silu_mul(acg[mi][nj][2], acu[mi][nj][2]),
                                       silu_mul(acg[mi][nj][3], acu[mi][nj][3]));
                *(float2*)(C + (size_t)(r0 + 8) * ldc + col) = v;
            }
        }
    }
}

// ================================================================
// GEMM 2 (unified): out += w * (A Wd^T), all via atomicAdd.
// z<16: A = g_inter[z] (K=512), scatter+weight.  z>=16: shared half.
// Block 128 M x 128 N, 3-stage ring.
// ================================================================
__global__ void __launch_bounds__(256, 2) mma_down_kernel(const float* __restrict__ dp,
                                                          const float* __restrict__ sd,
                                                          float* __restrict__ out) {
    const int z = blockIdx.z;
    const bool routed = z < E_;
    const int cnt = routed ? g_cnt[z] : T_;
    const int m0  = blockIdx.y * 128;
    if (m0 >= cnt) return;
    const int n0 = blockIdx.x * 128;

    const float* A;
    const float* W;
    int lda, ldw;
    if (routed) {
        A = g_inter + (size_t)z * T_ * INTER_; lda = INTER_;
        W = dp + (size_t)z * D_ * INTER_;      ldw = INTER_;
    } else {
        const int h = z - E_;
        A = g_hsh + (size_t)h * 512; lda = SH_INTER;
        W = sd    + (size_t)h * 512; ldw = SH_INTER;
    }

    extern __shared__ float smem[];
    float* As = smem;
    float* Bs = smem + NSTAGE * 128 * LDP;
    const uint32_t sA = smem_u32(As);
    const uint32_t sB = smem_u32(Bs);

    const int tid = threadIdx.x, wid = tid >> 5, lane = tid & 31;
    const int wm = wid >> 2, wn = wid & 3;

    const float* agl[4]; const float* bgl[4];
    uint32_t sa[4], sbo[4];
    #pragma unroll
    for (int t = 0; t < 4; t++) {
        int it = tid + 256 * t;
        int row = it >> 3, c4 = it & 7;
        int mm = m0 + row; if (mm > cnt - 1) mm = cnt - 1;
        agl[t] = A + (size_t)mm * lda + c4 * 4;
        bgl[t] = W + (size_t)(n0 + row) * ldw + c4 * 4;
        uint32_t boff = (uint32_t)(row * LDP + c4 * 4) * 4u;
        sa[t]  = sA + boff;
        sbo[t] = sB + boff;
    }

    float acc[4][4][4];
    #pragma unroll
    for (int mi = 0; mi < 4; mi++)
        #pragma unroll
        for (int nj = 0; nj < 4; nj++)
            #pragma unroll
            for (int r = 0; r < 4; r++) acc[mi][nj][r] = 0.f;

    const int NS = INTER_ / 32;   // 16 stages
    const int q = lane >> 2, c = lane & 3;

    #pragma unroll
    for (int p = 0; p < 2; p++) {
        const uint32_t bo = (uint32_t)(p * BUFB);
        #pragma unroll
        for (int t = 0; t < 4; t++) { cp16(sa[t] + bo, agl[t] + p * 32); cp16(sbo[t] + bo, bgl[t] + p * 32); }
        CP_COMMIT();
    }

    int buf = 0, pbuf = 2;
    for (int s = 0; s < NS; s++) {
        if (s + 1 < NS) CP_WAIT(1); else CP_WAIT(0);
        __syncthreads();
        if (s + 2 < NS) {
            const uint32_t bo = (uint32_t)(pbuf * BUFB);
            #pragma unroll
            for (int t = 0; t < 4; t++) {
                cp16(sa[t] + bo, agl[t] + (s + 2) * 32);
                cp16(sbo[t] + bo, bgl[t] + (s + 2) * 32);
            }
            CP_COMMIT();
        }

        const float* Ab = As + buf * 128 * LDP;
        const float* Bb = Bs + buf * 128 * LDP;
        #pragma unroll
        for (int ks = 0; ks < 4; ks++) {
            const int kc = ks * 8 + c;
            uint32_t af[4][4];
            #pragma unroll
            for (int mi = 0; mi < 4; mi++) {
                const int r = wm * 64 + mi * 16 + q;
                af[mi][0] = lds_tf32(&Ab[r * LDP + kc]);
                af[mi][1] = lds_tf32(&Ab[(r + 8) * LDP + kc]);
                af[mi][2] = lds_tf32(&Ab[r * LDP + kc + 4]);
                af[mi][3] = lds_tf32(&Ab[(r + 8) * LDP + kc + 4]);
            }
            #pragma unroll
            for (int nj = 0; nj < 4; nj++) {
                const int n = wn * 32 + nj * 8 + q;
                uint32_t b0 = lds_tf32(&Bb[n * LDP + kc]);
                uint32_t b1 = lds_tf32(&Bb[n * LDP + kc + 4]);
                #pragma unroll
                for (int mi = 0; mi < 4; mi++)
                    mma_tf32(acc[mi][nj], af[mi][0], af[mi][1], af[mi][2], af[mi][3], b0, b1);
            }
        }
        buf = (buf == NSTAGE - 1) ? 0 : buf + 1;
        pbuf = (pbuf == NSTAGE - 1) ? 0 : pbuf + 1;
    }

    // epilogue: all contributions atomically accumulate
    const int c2 = (lane & 3) * 2;
    #pragma unroll
    for (int mi = 0; mi < 4; mi++) {
        #pragma unroll
        for (int half = 0; half < 2; half++) {
            const int m = m0 + wm * 64 + mi * 16 + q + half * 8;
            if (m >= cnt) continue;
            const int   tok = routed ? g_tok[z * T_ + m] : m;
            const float wt  = routed ? g_wt [z * T_ + m] : 1.f;
            float* op = out + (size_t)tok * D_;
            #pragma unroll
            for (int nj = 0; nj < 4; nj++) {
                const int col = n0 + wn * 32 + nj * 8 + c2;
                atomicAdd(op + col,     wt * acc[mi][nj][half * 2 + 0]);
                atomicAdd(op + col + 1, wt * acc[mi][nj][half * 2 + 1]);
            }
        }
    }
}

// ---------------- launch ----------------
#define SMEM_BYTES (2 * NSTAGE * 128 * LDP * 4)   // 110592 B

extern "C" void kernel_launch(void* const* d_in, const int* in_sizes, int n_in,
                              void* d_out, int out_size) {
    const float* x  = (const float*)d_in[0];
    const float* gw = (const float*)d_in[2];
    const float* gb = (const float*)d_in[3];
    const float* gp = (const float*)d_in[4];
    const float* up = (const float*)d_in[5];
    const float* dp = (const float*)d_in[6];
    const float* sg = (const float*)d_in[7];
    const float* su = (const float*)d_in[8];
    const float* sd = (const float*)d_in[9];
    float* out = (float*)d_out;

    cudaFuncSetAttribute(mma_gu_kernel,   cudaFuncAttributeMaxDynamicSharedMemorySize, SMEM_BYTES);
    cudaFuncSetAttribute(mma_down_kernel, cudaFuncAttributeMaxDynamicSharedMemorySize, SMEM_BYTES);

    cudaMemsetAsync(out, 0, (size_t)T_ * D_ * sizeof(float), 0);
    zero_counts_kernel<<<1, 32>>>();
    route_kernel<<<T_, 128>>>(x, gw, gb);

    mma_gu_kernel<<<dim3(8, T_ / 128, NZ), 256, SMEM_BYTES>>>(x, gp, up, sg, su);
    mma_down_kernel<<<dim3(D_ / 128, T_ / 128, NZ), 256, SMEM_BYTES>>>(dp, sd, out);
}